// round 13
// baseline (speedup 1.0000x reference)
#include <cuda_runtime.h>

#define B_  32
#define D_  32
#define H_  256
#define W_  256
#define K_  512
#define TT  64                     // pair-tile size
#define NT  (K_ / TT)              // 8 tiles per image
#define NPAIRS (NT * (NT + 1) / 2) // 36 (ti <= tj)
#define NBLOCKS (B_ * NPAIRS)      // 1152
#define LTHREADS 128               // 16(kg) x 8(lg), 4x8 outputs each
#define GTHREADS 256
#define NTHREADS_TOTAL (NBLOCKS * LTHREADS)   // 147456, divisible by 32

typedef unsigned long long ull;

// Scratch: gathered pred, TRANSPOSED [B][D][K] (k contiguous), norms, tags.
__device__ float g_predT[B_ * D_ * K_];  // 2 MB
__device__ float g_ns[B_ * K_];
__device__ int   g_tag[B_ * K_];
// Device-wide barrier state (reset by last-passing block each launch).
__device__ unsigned g_cnt = 0;
__device__ unsigned g_passed = 0;

__device__ __forceinline__ float tanh_approx(float x) {
    float y;
    asm("tanh.approx.f32 %0, %1;" : "=f"(y) : "f"(x));
    return y;
}
__device__ __forceinline__ ull pack2(float lo, float hi) {
    ull r;
    asm("mov.b64 %0, {%1, %2};" : "=l"(r) : "f"(lo), "f"(hi));
    return r;
}
__device__ __forceinline__ void fma2(ull& acc, ull a, ull b) {
    asm("fma.rn.f32x2 %0, %1, %2, %0;" : "+l"(acc) : "l"(a), "l"(b));
}

union F4U { float4 f; ull u[2]; };
union UF  { ull u; float f[2]; };

// dtype probe: int64 => high dword of every value is 0 (values < 256);
// int32 => odd dwords uniform 0..255 (false-positive prob 256^-16).
__device__ __forceinline__ bool probe_is64(const void* kpts_raw) {
    const unsigned* kd = (const unsigned*)kpts_raw;
    bool is64 = true;
#pragma unroll
    for (int i = 1; i < 32; i += 2) is64 &= (__ldg(kd + i) == 0u);
    return is64;
}

__device__ __forceinline__ void read_point(const void* kpts_raw,
                                           const void* tags_raw, bool is64,
                                           int pt, int& r, int& c, int& tg) {
    if (is64) {
        const long long* kp  = (const long long*)kpts_raw;
        const long long* tgp = (const long long*)tags_raw;
        r  = (int)kp[(size_t)pt * 2 + 0];
        c  = (int)kp[(size_t)pt * 2 + 1];
        tg = (int)tgp[pt];
    } else {
        const int* kp  = (const int*)kpts_raw;
        const int* tgp = (const int*)tags_raw;
        r  = kp[(size_t)pt * 2 + 0];
        c  = kp[(size_t)pt * 2 + 1];
        tg = tgp[pt];
    }
    r = min(max(r, 0), H_ - 1);   // defensive: fail rel_err, not a crash
    c = min(max(c, 0), W_ - 1);
}

// Round-8 proven loss body: symmetry-halved 64x64 tile pair, 4(k)x8(l)
// per-thread outputs, packed fma.rn.f32x2 along l.
// psim = 2/(1+exp(x)) = 1 - tanh(x/2)  ->  e = tanh(arg) - neq.
__device__ __forceinline__ void loss_body(float* __restrict__ out, int t,
                                          int blk) {
    const int b = blk / NPAIRS;
    int p = blk % NPAIRS;
    int ti = 0;
    while (p >= NT - ti) { p -= (NT - ti); ++ti; }
    const int tj = ti + p;

    __shared__ float sI[D_ * TT];   // [d][k] 8 KB
    __shared__ float sJ[D_ * TT];   // [d][l] 8 KB
    __shared__ float nsI[TT], nsJ[TT];
    __shared__ int   tgI[TT], tgJ[TT];
    __shared__ float wsum[LTHREADS / 32];

    const float* srcI = g_predT + (size_t)b * D_ * K_ + ti * TT;
    const float* srcJ = g_predT + (size_t)b * D_ * K_ + tj * TT;

#pragma unroll
    for (int rr = 0; rr < 4; ++rr) {
        int idx4 = t + rr * LTHREADS;     // 0..511
        int d  = idx4 >> 4;
        int j4 = idx4 & 15;
        ((float4*)sI)[idx4] = *(const float4*)(srcI + (size_t)d * K_ + j4 * 4);
        ((float4*)sJ)[idx4] = *(const float4*)(srcJ + (size_t)d * K_ + j4 * 4);
    }
    {
        const int baseI = b * K_ + ti * TT;
        const int baseJ = b * K_ + tj * TT;
        if (t < TT) {
            nsI[t] = g_ns[baseI + t];    tgI[t] = g_tag[baseI + t];
        } else {
            nsJ[t - TT] = g_ns[baseJ + t - TT];
            tgJ[t - TT] = g_tag[baseJ + t - TT];
        }
    }
    __syncthreads();

    const int k0 = (t & 15) * 4;
    const int l0 = (t >> 4) * 4;

    ull acc2[4][4];
#pragma unroll
    for (int i = 0; i < 4; ++i)
#pragma unroll
        for (int j = 0; j < 4; ++j) acc2[i][j] = 0ull;

    const float* pI = sI + k0;
    const float* pJ = sJ + l0;
#pragma unroll 4
    for (int d = 0; d < D_; ++d) {
        float4 ka = *(const float4*)(pI + d * TT);
        F4U b0, b1;
        b0.f = *(const float4*)(pJ + d * TT);
        b1.f = *(const float4*)(pJ + d * TT + 32);
        ull lu[4] = {b0.u[0], b0.u[1], b1.u[0], b1.u[1]};
        ull kd2[4] = {pack2(ka.x, ka.x), pack2(ka.y, ka.y),
                      pack2(ka.z, ka.z), pack2(ka.w, ka.w)};
#pragma unroll
        for (int i = 0; i < 4; ++i)
#pragma unroll
            for (int j = 0; j < 4; ++j)
                fma2(acc2[i][j], kd2[i], lu[j]);
    }

    float nsk2[4], nsl2[8];
    int   tgk[4], tgl[8];
#pragma unroll
    for (int i = 0; i < 4; ++i) {
        nsk2[i] = nsI[k0 + i] * (1.0f / 64.0f);
        tgk[i]  = tgI[k0 + i];
        nsl2[i]     = nsJ[l0 + i]      * (1.0f / 64.0f);
        nsl2[i + 4] = nsJ[l0 + 32 + i] * (1.0f / 64.0f);
        tgl[i]      = tgJ[l0 + i];
        tgl[i + 4]  = tgJ[l0 + 32 + i];
    }

    float lsum = 0.0f;
#pragma unroll
    for (int i = 0; i < 4; ++i) {
#pragma unroll
        for (int jp = 0; jp < 4; ++jp) {
            UF v; v.u = acc2[i][jp];
            int j0 = (jp < 2) ? (2 * jp) : (4 + 2 * (jp - 2));
            int j1 = j0 + 1;
            float arg0 = fmaf(v.f[0], -1.0f / 32.0f, nsk2[i] + nsl2[j0]);
            float arg1 = fmaf(v.f[1], -1.0f / 32.0f, nsk2[i] + nsl2[j1]);
            float e0 = tanh_approx(arg0) - ((tgk[i] != tgl[j0]) ? 1.0f : 0.0f);
            float e1 = tanh_approx(arg1) - ((tgk[i] != tgl[j1]) ? 1.0f : 0.0f);
            lsum += e0 * e0 + e1 * e1;
        }
    }

#pragma unroll
    for (int o = 16; o > 0; o >>= 1)
        lsum += __shfl_down_sync(0xffffffffu, lsum, o);
    if ((t & 31) == 0) wsum[t >> 5] = lsum;
    __syncthreads();
    if (t == 0) {
        float w = (ti == tj) ? 1.0f : 2.0f;
        float s = wsum[0] + wsum[1] + wsum[2] + wsum[3];
        atomicAdd(out, s * w * (1.0f / ((float)B_ * (float)K_ * (float)K_)));
    }
}

// ---------- Fallback path: two kernels (round-8 proven, 18.5 us) ----------

__global__ void gather_kernel(const float* __restrict__ ebd,
                              const void* __restrict__ kpts_raw,
                              const void* __restrict__ tags_raw,
                              float* __restrict__ out) {
    if (blockIdx.x == 0 && threadIdx.x == 0) out[0] = 0.0f;

    int tid = blockIdx.x * blockDim.x + threadIdx.x;   // 4*(b*K + k) + h
    if (tid >= B_ * K_ * 4) return;
    int idx = tid >> 2;
    int h   = tid & 3;

    bool is64 = probe_is64(kpts_raw);
    int r, c, tg;
    read_point(kpts_raw, tags_raw, is64, idx, r, c, tg);

    int b = idx >> 9;
    int k = idx & (K_ - 1);
    const int d0 = h * (D_ / 4);
    const float* base = ebd + (size_t)b * D_ * H_ * W_ + (size_t)d0 * (H_ * W_)
                            + (size_t)r * W_ + (size_t)c;
    float* dstT = g_predT + (size_t)b * D_ * K_ + (size_t)d0 * K_ + k;
    float ns = 0.0f;
#pragma unroll
    for (int d = 0; d < D_ / 4; ++d) {
        float x = base[(size_t)d * (H_ * W_)];
        dstT[(size_t)d * K_] = x;
        ns += x * x;
    }
    ns += __shfl_xor_sync(0xffffffffu, ns, 1);
    ns += __shfl_xor_sync(0xffffffffu, ns, 2);
    if (h == 0) {
        g_ns[idx]  = ns;
        g_tag[idx] = tg;
    }
}

__global__ __launch_bounds__(LTHREADS) void loss_kernel(float* __restrict__ out) {
    loss_body(out, threadIdx.x, blockIdx.x);
}

// ---------- Fused path: gather + device barrier + loss, single launch ----
// ONLY launched when the occupancy API proves all NBLOCKS are co-resident
// (spin barrier is deadlock-free by construction under that gate).

__global__ __launch_bounds__(LTHREADS, 8) void fused_kernel(
        const float* __restrict__ ebd,
        const void* __restrict__ kpts_raw,
        const void* __restrict__ tags_raw,
        float* __restrict__ out) {
    const int t = threadIdx.x;

    if (blockIdx.x == 0 && t == 0) out[0] = 0.0f;

    // Phase 1: gather. B*K*D = 524288 elements > 147456 threads, so
    // GRID-STRIDE (round-11/12 bug: single-shot covered only 28% of points).
    // Stride is a multiple of 32, so within each iteration a warp maps to
    // one point (lane = channel) and the butterfly reduce is valid.
    {
        const bool is64 = probe_is64(kpts_raw);
        int gtid = blockIdx.x * LTHREADS + t;
        for (int e = gtid; e < B_ * K_ * D_; e += NTHREADS_TOTAL) {
            int pt = e >> 5;            // warp-uniform point index
            int d  = e & 31;            // channel = lane

            int r, c, tg;
            read_point(kpts_raw, tags_raw, is64, pt, r, c, tg);

            int b = pt >> 9;
            int k = pt & (K_ - 1);
            float x = ebd[(size_t)b * D_ * H_ * W_ + (size_t)d * (H_ * W_)
                          + (size_t)r * W_ + (size_t)c];
            g_predT[(size_t)b * D_ * K_ + (size_t)d * K_ + k] = x;

            float ns = x * x;
#pragma unroll
            for (int o = 16; o > 0; o >>= 1)
                ns += __shfl_xor_sync(0xffffffffu, ns, o);
            if (d == 0) {
                g_ns[pt]  = ns;
                g_tag[pt] = tg;
            }
        }
    }

    // Block-level barrier BEFORE the device-wide arrive: all 128 threads'
    // gather stores complete before thread 0 releases them device-wide.
    __syncthreads();

    // Device-wide barrier (all blocks co-resident, guaranteed by host gate).
    if (t == 0) {
        __threadfence();
        atomicAdd(&g_cnt, 1u);
        while (*((volatile unsigned*)&g_cnt) < (unsigned)NBLOCKS)
            __nanosleep(64);
        __threadfence();
    }
    __syncthreads();

    // Phase 2: loss.
    loss_body(out, t, blockIdx.x);

    // Barrier reset for the next graph replay: last-passing block resets.
    if (t == 0) {
        unsigned pdone = atomicAdd(&g_passed, 1u);
        if (pdone == (unsigned)(NBLOCKS - 1)) {
            g_cnt = 0u;
            g_passed = 0u;
            __threadfence();
        }
    }
}

extern "C" void kernel_launch(void* const* d_in, const int* in_sizes, int n_in,
                              void* d_out, int out_size) {
    const float* ebd  = (const float*)d_in[0];
    const void*  kpts = (const void*)d_in[1];
    const void*  tags = (const void*)d_in[2];
    float* out = (float*)d_out;

    (void)in_sizes; (void)n_in; (void)out_size;

    // Decide once (deterministic for a fixed device/driver): fused spin-
    // barrier kernel is legal ONLY if all NBLOCKS fit in one wave.
    static int mode = -1;
    if (mode < 0) {
        cudaFuncSetAttribute(fused_kernel,
                             cudaFuncAttributePreferredSharedMemoryCarveout, 100);
        int dev = 0, nsm = 0, blk_per_sm = 0;
        cudaGetDevice(&dev);
        cudaDeviceGetAttribute(&nsm, cudaDevAttrMultiProcessorCount, dev);
        cudaError_t e = cudaOccupancyMaxActiveBlocksPerMultiprocessor(
            &blk_per_sm, fused_kernel, LTHREADS, 0);
        mode = (e == cudaSuccess && blk_per_sm * nsm >= NBLOCKS) ? 1 : 0;
    }

    if (mode == 1) {
        fused_kernel<<<NBLOCKS, LTHREADS>>>(ebd, kpts, tags, out);
    } else {
        gather_kernel<<<(B_ * K_ * 4 + GTHREADS - 1) / GTHREADS, GTHREADS>>>(
            ebd, kpts, tags, out);
        loss_kernel<<<NBLOCKS, LTHREADS>>>(out);
    }
}

// round 14
// speedup vs baseline: 1.0960x; 1.0960x over previous
#include <cuda_runtime.h>

#define B_  32
#define D_  32
#define H_  256
#define W_  256
#define K_  512
#define TT  64                     // pair-tile size
#define NT  (K_ / TT)              // 8 tiles per image
#define NPAIRS (NT * (NT + 1) / 2) // 36 (ti <= tj)
#define NBLOCKS (B_ * NPAIRS)      // 1152
#define LTHREADS 128               // 16(kg) x 8(lg), 4x8 outputs each
#define GTHREADS 256

typedef unsigned long long ull;

// Scratch: gathered pred, TRANSPOSED [B][D][K] (k contiguous), norms, tags.
__device__ float g_predT[B_ * D_ * K_];  // 2 MB
__device__ float g_ns[B_ * K_];
__device__ int   g_tag[B_ * K_];
// Device-wide barrier state (reset by last-passing block each launch).
__device__ unsigned g_cnt = 0;
__device__ unsigned g_passed = 0;

__device__ __forceinline__ float tanh_approx(float x) {
    float y;
    asm("tanh.approx.f32 %0, %1;" : "=f"(y) : "f"(x));
    return y;
}
__device__ __forceinline__ ull pack2(float lo, float hi) {
    ull r;
    asm("mov.b64 %0, {%1, %2};" : "=l"(r) : "f"(lo), "f"(hi));
    return r;
}
__device__ __forceinline__ void fma2(ull& acc, ull a, ull b) {
    asm("fma.rn.f32x2 %0, %1, %2, %0;" : "+l"(acc) : "l"(a), "l"(b));
}

union F4U { float4 f; ull u[2]; };
union UF  { ull u; float f[2]; };

// dtype probe: int64 => high dword of every value is 0 (values < 256);
// int32 => odd dwords uniform 0..255 (false-positive prob 256^-16).
__device__ __forceinline__ bool probe_is64(const void* kpts_raw) {
    const unsigned* kd = (const unsigned*)kpts_raw;
    bool is64 = true;
#pragma unroll
    for (int i = 1; i < 32; i += 2) is64 &= (__ldg(kd + i) == 0u);
    return is64;
}

__device__ __forceinline__ void read_point(const void* kpts_raw,
                                           const void* tags_raw, bool is64,
                                           int pt, int& r, int& c, int& tg) {
    if (is64) {
        const long long* kp  = (const long long*)kpts_raw;
        const long long* tgp = (const long long*)tags_raw;
        r  = (int)kp[(size_t)pt * 2 + 0];
        c  = (int)kp[(size_t)pt * 2 + 1];
        tg = (int)tgp[pt];
    } else {
        const int* kp  = (const int*)kpts_raw;
        const int* tgp = (const int*)tags_raw;
        r  = kp[(size_t)pt * 2 + 0];
        c  = kp[(size_t)pt * 2 + 1];
        tg = tgp[pt];
    }
    r = min(max(r, 0), H_ - 1);   // defensive: fail rel_err, not a crash
    c = min(max(c, 0), W_ - 1);
}

// High-MLP gather body: 4 threads per point, 8 independent channel LDGs
// each (MLP=8), 2-stage shfl to combine ||p||^2. Writes d-major g_predT.
__device__ __forceinline__ void gather_body(const float* __restrict__ ebd,
                                            const void* __restrict__ kpts_raw,
                                            const void* __restrict__ tags_raw,
                                            int tid) {
    int idx = tid >> 2;            // point index b*K + k
    int h   = tid & 3;             // d-quarter

    bool is64 = probe_is64(kpts_raw);
    int r, c, tg;
    read_point(kpts_raw, tags_raw, is64, idx, r, c, tg);

    int b = idx >> 9;
    int k = idx & (K_ - 1);
    const int d0 = h * (D_ / 4);
    const float* base = ebd + (size_t)b * D_ * H_ * W_ + (size_t)d0 * (H_ * W_)
                            + (size_t)r * W_ + (size_t)c;
    float* dstT = g_predT + (size_t)b * D_ * K_ + (size_t)d0 * K_ + k;
    float ns = 0.0f;
#pragma unroll
    for (int d = 0; d < D_ / 4; ++d) {
        float x = base[(size_t)d * (H_ * W_)];
        dstT[(size_t)d * K_] = x;
        ns += x * x;
    }
    ns += __shfl_xor_sync(0xffffffffu, ns, 1);
    ns += __shfl_xor_sync(0xffffffffu, ns, 2);
    if (h == 0) {
        g_ns[idx]  = ns;
        g_tag[idx] = tg;
    }
}

// Round-8 proven loss body: symmetry-halved 64x64 tile pair, 4(k)x8(l)
// per-thread outputs, packed fma.rn.f32x2 along l.
// psim = 2/(1+exp(x)) = 1 - tanh(x/2)  ->  e = tanh(arg) - neq.
__device__ __forceinline__ void loss_body(float* __restrict__ out, int t,
                                          int blk) {
    const int b = blk / NPAIRS;
    int p = blk % NPAIRS;
    int ti = 0;
    while (p >= NT - ti) { p -= (NT - ti); ++ti; }
    const int tj = ti + p;

    __shared__ float sI[D_ * TT];   // [d][k] 8 KB
    __shared__ float sJ[D_ * TT];   // [d][l] 8 KB
    __shared__ float nsI[TT], nsJ[TT];
    __shared__ int   tgI[TT], tgJ[TT];
    __shared__ float wsum[LTHREADS / 32];

    const float* srcI = g_predT + (size_t)b * D_ * K_ + ti * TT;
    const float* srcJ = g_predT + (size_t)b * D_ * K_ + tj * TT;

#pragma unroll
    for (int rr = 0; rr < 4; ++rr) {
        int idx4 = t + rr * LTHREADS;     // 0..511
        int d  = idx4 >> 4;
        int j4 = idx4 & 15;
        ((float4*)sI)[idx4] = *(const float4*)(srcI + (size_t)d * K_ + j4 * 4);
        ((float4*)sJ)[idx4] = *(const float4*)(srcJ + (size_t)d * K_ + j4 * 4);
    }
    {
        const int baseI = b * K_ + ti * TT;
        const int baseJ = b * K_ + tj * TT;
        if (t < TT) {
            nsI[t] = g_ns[baseI + t];    tgI[t] = g_tag[baseI + t];
        } else {
            nsJ[t - TT] = g_ns[baseJ + t - TT];
            tgJ[t - TT] = g_tag[baseJ + t - TT];
        }
    }
    __syncthreads();

    const int k0 = (t & 15) * 4;
    const int l0 = (t >> 4) * 4;

    ull acc2[4][4];
#pragma unroll
    for (int i = 0; i < 4; ++i)
#pragma unroll
        for (int j = 0; j < 4; ++j) acc2[i][j] = 0ull;

    const float* pI = sI + k0;
    const float* pJ = sJ + l0;
#pragma unroll 4
    for (int d = 0; d < D_; ++d) {
        float4 ka = *(const float4*)(pI + d * TT);
        F4U b0, b1;
        b0.f = *(const float4*)(pJ + d * TT);
        b1.f = *(const float4*)(pJ + d * TT + 32);
        ull lu[4] = {b0.u[0], b0.u[1], b1.u[0], b1.u[1]};
        ull kd2[4] = {pack2(ka.x, ka.x), pack2(ka.y, ka.y),
                      pack2(ka.z, ka.z), pack2(ka.w, ka.w)};
#pragma unroll
        for (int i = 0; i < 4; ++i)
#pragma unroll
            for (int j = 0; j < 4; ++j)
                fma2(acc2[i][j], kd2[i], lu[j]);
    }

    float nsk2[4], nsl2[8];
    int   tgk[4], tgl[8];
#pragma unroll
    for (int i = 0; i < 4; ++i) {
        nsk2[i] = nsI[k0 + i] * (1.0f / 64.0f);
        tgk[i]  = tgI[k0 + i];
        nsl2[i]     = nsJ[l0 + i]      * (1.0f / 64.0f);
        nsl2[i + 4] = nsJ[l0 + 32 + i] * (1.0f / 64.0f);
        tgl[i]      = tgJ[l0 + i];
        tgl[i + 4]  = tgJ[l0 + 32 + i];
    }

    float lsum = 0.0f;
#pragma unroll
    for (int i = 0; i < 4; ++i) {
#pragma unroll
        for (int jp = 0; jp < 4; ++jp) {
            UF v; v.u = acc2[i][jp];
            int j0 = (jp < 2) ? (2 * jp) : (4 + 2 * (jp - 2));
            int j1 = j0 + 1;
            float arg0 = fmaf(v.f[0], -1.0f / 32.0f, nsk2[i] + nsl2[j0]);
            float arg1 = fmaf(v.f[1], -1.0f / 32.0f, nsk2[i] + nsl2[j1]);
            float e0 = tanh_approx(arg0) - ((tgk[i] != tgl[j0]) ? 1.0f : 0.0f);
            float e1 = tanh_approx(arg1) - ((tgk[i] != tgl[j1]) ? 1.0f : 0.0f);
            lsum += e0 * e0 + e1 * e1;
        }
    }

#pragma unroll
    for (int o = 16; o > 0; o >>= 1)
        lsum += __shfl_down_sync(0xffffffffu, lsum, o);
    if ((t & 31) == 0) wsum[t >> 5] = lsum;
    __syncthreads();
    if (t == 0) {
        float w = (ti == tj) ? 1.0f : 2.0f;
        float s = wsum[0] + wsum[1] + wsum[2] + wsum[3];
        atomicAdd(out, s * w * (1.0f / ((float)B_ * (float)K_ * (float)K_)));
    }
}

// ---------- Fallback path: two kernels (round-8 proven, 18.5 us) ----------

__global__ void gather_kernel(const float* __restrict__ ebd,
                              const void* __restrict__ kpts_raw,
                              const void* __restrict__ tags_raw,
                              float* __restrict__ out) {
    if (blockIdx.x == 0 && threadIdx.x == 0) out[0] = 0.0f;
    int tid = blockIdx.x * blockDim.x + threadIdx.x;
    if (tid >= B_ * K_ * 4) return;
    gather_body(ebd, kpts_raw, tags_raw, tid);
}

__global__ __launch_bounds__(LTHREADS) void loss_kernel(float* __restrict__ out) {
    loss_body(out, threadIdx.x, blockIdx.x);
}

// ---------- Fused path: gather + device barrier + loss, single launch ----
// ONLY launched when the occupancy API proves all NBLOCKS are co-resident
// (spin barrier is deadlock-free by construction under that gate).

__global__ __launch_bounds__(LTHREADS, 8) void fused_kernel(
        const float* __restrict__ ebd,
        const void* __restrict__ kpts_raw,
        const void* __restrict__ tags_raw,
        float* __restrict__ out) {
    const int t = threadIdx.x;

    if (blockIdx.x == 0 && t == 0) out[0] = 0.0f;

    // Phase 1: gather in the first 512 blocks only (65536 threads = 4 per
    // point x 16384 points), MLP=8 per thread — same shape as the proven
    // standalone gather (round-13 regression was the MLP=1 grid-stride
    // variant). Remaining 640 blocks proceed straight to the barrier.
    int gtid = blockIdx.x * LTHREADS + t;
    if (gtid < B_ * K_ * 4) {
        gather_body(ebd, kpts_raw, tags_raw, gtid);
    }

    // Block-level barrier BEFORE the device-wide arrive: all 128 threads'
    // gather stores complete before thread 0 releases them device-wide.
    __syncthreads();

    // Device-wide barrier (all blocks co-resident, guaranteed by host gate).
    if (t == 0) {
        __threadfence();
        atomicAdd(&g_cnt, 1u);
        while (*((volatile unsigned*)&g_cnt) < (unsigned)NBLOCKS)
            __nanosleep(64);
        __threadfence();
    }
    __syncthreads();

    // Phase 2: loss.
    loss_body(out, t, blockIdx.x);

    // Barrier reset for the next graph replay: last-passing block resets.
    if (t == 0) {
        unsigned pdone = atomicAdd(&g_passed, 1u);
        if (pdone == (unsigned)(NBLOCKS - 1)) {
            g_cnt = 0u;
            g_passed = 0u;
            __threadfence();
        }
    }
}

extern "C" void kernel_launch(void* const* d_in, const int* in_sizes, int n_in,
                              void* d_out, int out_size) {
    const float* ebd  = (const float*)d_in[0];
    const void*  kpts = (const void*)d_in[1];
    const void*  tags = (const void*)d_in[2];
    float* out = (float*)d_out;

    (void)in_sizes; (void)n_in; (void)out_size;

    // Decide once (deterministic for a fixed device/driver): fused spin-
    // barrier kernel is legal ONLY if all NBLOCKS fit in one wave.
    static int mode = -1;
    if (mode < 0) {
        cudaFuncSetAttribute(fused_kernel,
                             cudaFuncAttributePreferredSharedMemoryCarveout, 100);
        int dev = 0, nsm = 0, blk_per_sm = 0;
        cudaGetDevice(&dev);
        cudaDeviceGetAttribute(&nsm, cudaDevAttrMultiProcessorCount, dev);
        cudaError_t e = cudaOccupancyMaxActiveBlocksPerMultiprocessor(
            &blk_per_sm, fused_kernel, LTHREADS, 0);
        mode = (e == cudaSuccess && blk_per_sm * nsm >= NBLOCKS) ? 1 : 0;
    }

    if (mode == 1) {
        fused_kernel<<<NBLOCKS, LTHREADS>>>(ebd, kpts, tags, out);
    } else {
        gather_kernel<<<(B_ * K_ * 4 + GTHREADS - 1) / GTHREADS, GTHREADS>>>(
            ebd, kpts, tags, out);
        loss_kernel<<<NBLOCKS, LTHREADS>>>(out);
    }
}

// round 15
// speedup vs baseline: 1.1675x; 1.0652x over previous
#include <cuda_runtime.h>

#define B_  32
#define D_  32
#define H_  256
#define W_  256
#define K_  512
#define TT  64                     // pair-tile size
#define NT  (K_ / TT)              // 8 tiles per image
#define NPAIRS (NT * (NT + 1) / 2) // 36 (ti <= tj)
#define NBLOCKS (B_ * NPAIRS)      // 1152
#define LTHREADS 128               // 16(kg) x 8(lg), 4x8 outputs each
#define GTHREADS 256

typedef unsigned long long ull;

// Scratch: gathered pred, TRANSPOSED [B][D][K] (k contiguous), norms, tags.
__device__ float g_predT[B_ * D_ * K_];  // 2 MB
__device__ float g_ns[B_ * K_];
__device__ int   g_tag[B_ * K_];

__device__ __forceinline__ float tanh_approx(float x) {
    float y;
    asm("tanh.approx.f32 %0, %1;" : "=f"(y) : "f"(x));
    return y;
}
__device__ __forceinline__ void fma2(ull& acc, ull a, ull b) {
    asm("fma.rn.f32x2 %0, %1, %2, %0;" : "+l"(acc) : "l"(a), "l"(b));
}

union F4U { float4 f; ull u[2]; };
union UF  { ull u; float f[2]; };

// dtype probe: int64 => high dword of every value is 0 (values < 256);
// int32 => odd dwords uniform 0..255 (false-positive prob 256^-16).
__device__ __forceinline__ bool probe_is64(const void* kpts_raw) {
    const unsigned* kd = (const unsigned*)kpts_raw;
    bool is64 = true;
#pragma unroll
    for (int i = 1; i < 32; i += 2) is64 &= (__ldg(kd + i) == 0u);
    return is64;
}

__device__ __forceinline__ void read_point(const void* kpts_raw,
                                           const void* tags_raw, bool is64,
                                           int pt, int& r, int& c, int& tg) {
    if (is64) {
        const long long* kp  = (const long long*)kpts_raw;
        const long long* tgp = (const long long*)tags_raw;
        r  = (int)kp[(size_t)pt * 2 + 0];
        c  = (int)kp[(size_t)pt * 2 + 1];
        tg = (int)tgp[pt];
    } else {
        const int* kp  = (const int*)kpts_raw;
        const int* tgp = (const int*)tags_raw;
        r  = kp[(size_t)pt * 2 + 0];
        c  = kp[(size_t)pt * 2 + 1];
        tg = tgp[pt];
    }
    r = min(max(r, 0), H_ - 1);   // defensive: fail rel_err, not a crash
    c = min(max(c, 0), W_ - 1);
}

// Gather: 4 threads per point, 8 independent channel LDGs each (MLP=8),
// 2-stage shfl to combine ||p||^2. Writes d-major g_predT. Also zeroes out.
__global__ void gather_kernel(const float* __restrict__ ebd,
                              const void* __restrict__ kpts_raw,
                              const void* __restrict__ tags_raw,
                              float* __restrict__ out) {
    if (blockIdx.x == 0 && threadIdx.x == 0) out[0] = 0.0f;

    int tid = blockIdx.x * blockDim.x + threadIdx.x;   // 4*(b*K + k) + h
    if (tid >= B_ * K_ * 4) return;
    int idx = tid >> 2;            // point index b*K + k
    int h   = tid & 3;             // d-quarter

    bool is64 = probe_is64(kpts_raw);
    int r, c, tg;
    read_point(kpts_raw, tags_raw, is64, idx, r, c, tg);

    int b = idx >> 9;
    int k = idx & (K_ - 1);
    const int d0 = h * (D_ / 4);
    const float* base = ebd + (size_t)b * D_ * H_ * W_ + (size_t)d0 * (H_ * W_)
                            + (size_t)r * W_ + (size_t)c;
    float* dstT = g_predT + (size_t)b * D_ * K_ + (size_t)d0 * K_ + k;
    float ns = 0.0f;
#pragma unroll
    for (int d = 0; d < D_ / 4; ++d) {
        float x = base[(size_t)d * (H_ * W_)];
        dstT[(size_t)d * K_] = x;
        ns += x * x;
    }
    ns += __shfl_xor_sync(0xffffffffu, ns, 1);
    ns += __shfl_xor_sync(0xffffffffu, ns, 2);
    if (h == 0) {
        g_ns[idx]  = ns;
        g_tag[idx] = tg;
    }
}

// Symmetry-halved pairwise loss, round-8 layout with the I(k) tile stored
// PRE-DUPLICATED in smem: the (k,k) FMA2 operand is a direct LDS.128,
// eliminating the 4 mov.b64 packs per warp-d (23 -> 20 inner issue slots).
// Thread t: k in {k0..k0+3} (k0=(t&15)*4),
//           l in {l0..l0+3, l0+32..l0+35} (l0=(t>>4)*4).
// psim = 2/(1+exp(x)) = 1 - tanh(x/2)  ->  e = tanh(arg) - neq.
__global__ __launch_bounds__(LTHREADS) void loss_kernel(float* __restrict__ out) {
    const int b = blockIdx.x / NPAIRS;
    int p = blockIdx.x % NPAIRS;
    int ti = 0;
    while (p >= NT - ti) { p -= (NT - ti); ++ti; }
    const int tj = ti + p;

    __shared__ float sId[D_ * TT * 2];  // [d][2k dup] 16 KB
    __shared__ float sJ [D_ * TT];      // [d][l]       8 KB
    __shared__ float nsI[TT], nsJ[TT];
    __shared__ int   tgI[TT], tgJ[TT];
    __shared__ float wsum[LTHREADS / 32];

    const int t = threadIdx.x;
    const float* srcI = g_predT + (size_t)b * D_ * K_ + ti * TT;
    const float* srcJ = g_predT + (size_t)b * D_ * K_ + tj * TT;

    // Fill: 512 source float4 per tile, 4 per thread. Row d = 16 float4.
    // I written duplicated (row d = 32 float4), J written normally.
#pragma unroll
    for (int rr = 0; rr < 4; ++rr) {
        int idx4 = t + rr * LTHREADS;     // 0..511
        int d  = idx4 >> 4;
        int j4 = idx4 & 15;
        float4 vi = *(const float4*)(srcI + (size_t)d * K_ + j4 * 4);
        ((float4*)sId)[d * 32 + j4 * 2]     = make_float4(vi.x, vi.x, vi.y, vi.y);
        ((float4*)sId)[d * 32 + j4 * 2 + 1] = make_float4(vi.z, vi.z, vi.w, vi.w);
        ((float4*)sJ)[idx4] = *(const float4*)(srcJ + (size_t)d * K_ + j4 * 4);
    }
    {
        const int baseI = b * K_ + ti * TT;
        const int baseJ = b * K_ + tj * TT;
        if (t < TT) {
            nsI[t] = g_ns[baseI + t];    tgI[t] = g_tag[baseI + t];
        } else {
            nsJ[t - TT] = g_ns[baseJ + t - TT];
            tgJ[t - TT] = g_tag[baseJ + t - TT];
        }
    }
    __syncthreads();

    const int k0 = (t & 15) * 4;
    const int l0 = (t >> 4) * 4;

    // acc2[i][jp]: k_{k0+i} x packed l-pair jp:
    //   jp0 -> (l0, l0+1), jp1 -> (l0+2, l0+3),
    //   jp2 -> (l0+32, l0+33), jp3 -> (l0+34, l0+35).
    ull acc2[4][4];
#pragma unroll
    for (int i = 0; i < 4; ++i)
#pragma unroll
        for (int j = 0; j < 4; ++j) acc2[i][j] = 0ull;

    const float* pI = sId + 2 * k0;     // duplicated row: 2*TT floats per d
    const float* pJ = sJ + l0;
#pragma unroll 4
    for (int d = 0; d < D_; ++d) {
        F4U a0, a1, b0, b1;
        a0.f = *(const float4*)(pI + d * (2 * TT));      // (k0,k0),(k0+1,k0+1)
        a1.f = *(const float4*)(pI + d * (2 * TT) + 4);  // (k0+2,k0+2),(k0+3,k0+3)
        b0.f = *(const float4*)(pJ + d * TT);            // warp-broadcast
        b1.f = *(const float4*)(pJ + d * TT + 32);       // warp-broadcast
        ull kd2[4] = {a0.u[0], a0.u[1], a1.u[0], a1.u[1]};
        ull lu[4]  = {b0.u[0], b0.u[1], b1.u[0], b1.u[1]};
#pragma unroll
        for (int i = 0; i < 4; ++i)
#pragma unroll
            for (int j = 0; j < 4; ++j)
                fma2(acc2[i][j], kd2[i], lu[j]);
    }

    // Epilogue: 32 pairs. arg = (nsk + nsl - 2*dot)/64; e = tanh(arg) - neq.
    float nsk2[4], nsl2[8];
    int   tgk[4], tgl[8];
#pragma unroll
    for (int i = 0; i < 4; ++i) {
        nsk2[i] = nsI[k0 + i] * (1.0f / 64.0f);
        tgk[i]  = tgI[k0 + i];
        nsl2[i]     = nsJ[l0 + i]      * (1.0f / 64.0f);
        nsl2[i + 4] = nsJ[l0 + 32 + i] * (1.0f / 64.0f);
        tgl[i]      = tgJ[l0 + i];
        tgl[i + 4]  = tgJ[l0 + 32 + i];
    }

    float lsum = 0.0f;
#pragma unroll
    for (int i = 0; i < 4; ++i) {
#pragma unroll
        for (int jp = 0; jp < 4; ++jp) {
            UF v; v.u = acc2[i][jp];
            int j0 = (jp < 2) ? (2 * jp) : (4 + 2 * (jp - 2));
            int j1 = j0 + 1;
            float arg0 = fmaf(v.f[0], -1.0f / 32.0f, nsk2[i] + nsl2[j0]);
            float arg1 = fmaf(v.f[1], -1.0f / 32.0f, nsk2[i] + nsl2[j1]);
            float e0 = tanh_approx(arg0) - ((tgk[i] != tgl[j0]) ? 1.0f : 0.0f);
            float e1 = tanh_approx(arg1) - ((tgk[i] != tgl[j1]) ? 1.0f : 0.0f);
            lsum += e0 * e0 + e1 * e1;
        }
    }

    // Block reduction (4 warps) + weighted atomic.
#pragma unroll
    for (int o = 16; o > 0; o >>= 1)
        lsum += __shfl_down_sync(0xffffffffu, lsum, o);
    if ((t & 31) == 0) wsum[t >> 5] = lsum;
    __syncthreads();
    if (t == 0) {
        float w = (ti == tj) ? 1.0f : 2.0f;
        float s = wsum[0] + wsum[1] + wsum[2] + wsum[3];
        atomicAdd(out, s * w * (1.0f / ((float)B_ * (float)K_ * (float)K_)));
    }
}

extern "C" void kernel_launch(void* const* d_in, const int* in_sizes, int n_in,
                              void* d_out, int out_size) {
    const float* ebd  = (const float*)d_in[0];
    const void*  kpts = (const void*)d_in[1];
    const void*  tags = (const void*)d_in[2];
    float* out = (float*)d_out;

    (void)in_sizes; (void)n_in; (void)out_size;

    gather_kernel<<<(B_ * K_ * 4 + GTHREADS - 1) / GTHREADS, GTHREADS>>>(
        ebd, kpts, tags, out);
    loss_kernel<<<NBLOCKS, LTHREADS>>>(out);
}

// round 16
// speedup vs baseline: 2.0334x; 1.7416x over previous
#include <cuda_runtime.h>

#define B_  32
#define D_  32
#define H_  256
#define W_  256
#define K_  512
#define TT  64                     // pair-tile size
#define NT  (K_ / TT)              // 8 tiles per image
#define NPAIRS (NT * (NT + 1) / 2) // 36 (ti <= tj)
#define NBLOCKS (B_ * NPAIRS)      // 1152
#define LTHREADS 128               // 4 warps; warp w covers k rows w*16..w*16+15
#define GTHREADS 256
#define SPAD 72                    // smem row stride (floats): (8*tig+g)&31 distinct

typedef unsigned uint32;

// Scratch: gathered pred (tf32-rounded), TRANSPOSED [B][D][K], norms, tags.
__device__ float g_predT[B_ * D_ * K_];  // 2 MB
__device__ float g_ns[B_ * K_];
__device__ int   g_tag[B_ * K_];

__device__ __forceinline__ float tanh_approx(float x) {
    float y;
    asm("tanh.approx.f32 %0, %1;" : "=f"(y) : "f"(x));
    return y;
}
__device__ __forceinline__ float tf32_round(float x) {
    uint32 u;
    asm("cvt.rna.tf32.f32 %0, %1;" : "=r"(u) : "f"(x));
    return __uint_as_float(u);
}
__device__ __forceinline__ void mma_tf32(float& c0, float& c1, float& c2, float& c3,
                                         uint32 a0, uint32 a1, uint32 a2, uint32 a3,
                                         uint32 b0, uint32 b1) {
    asm("mma.sync.aligned.m16n8k8.row.col.f32.tf32.tf32.f32 "
        "{%0,%1,%2,%3}, {%4,%5,%6,%7}, {%8,%9}, {%0,%1,%2,%3};"
        : "+f"(c0), "+f"(c1), "+f"(c2), "+f"(c3)
        : "r"(a0), "r"(a1), "r"(a2), "r"(a3), "r"(b0), "r"(b1));
}

// dtype probe: int64 => high dword of every value is 0 (values < 256);
// int32 => odd dwords uniform 0..255 (false-positive prob 256^-16).
__device__ __forceinline__ bool probe_is64(const void* kpts_raw) {
    const uint32* kd = (const uint32*)kpts_raw;
    bool is64 = true;
#pragma unroll
    for (int i = 1; i < 32; i += 2) is64 &= (__ldg(kd + i) == 0u);
    return is64;
}

__device__ __forceinline__ void read_point(const void* kpts_raw,
                                           const void* tags_raw, bool is64,
                                           int pt, int& r, int& c, int& tg) {
    if (is64) {
        const long long* kp  = (const long long*)kpts_raw;
        const long long* tgp = (const long long*)tags_raw;
        r  = (int)kp[(size_t)pt * 2 + 0];
        c  = (int)kp[(size_t)pt * 2 + 1];
        tg = (int)tgp[pt];
    } else {
        const int* kp  = (const int*)kpts_raw;
        const int* tgp = (const int*)tags_raw;
        r  = kp[(size_t)pt * 2 + 0];
        c  = kp[(size_t)pt * 2 + 1];
        tg = tgp[pt];
    }
    r = min(max(r, 0), H_ - 1);   // defensive: fail rel_err, not a crash
    c = min(max(c, 0), W_ - 1);
}

// Gather: 4 threads/point, 8 independent channel LDGs each (MLP=8).
// Stores tf32-ROUNDED values; ||p||^2 computed from the rounded values so
// the Gram diagonal identity (expo_kk ~ 0) is preserved under tf32 MMA.
__global__ void gather_kernel(const float* __restrict__ ebd,
                              const void* __restrict__ kpts_raw,
                              const void* __restrict__ tags_raw,
                              float* __restrict__ out) {
    if (blockIdx.x == 0 && threadIdx.x == 0) out[0] = 0.0f;

    int tid = blockIdx.x * blockDim.x + threadIdx.x;   // 4*(b*K + k) + h
    if (tid >= B_ * K_ * 4) return;
    int idx = tid >> 2;            // point index b*K + k
    int h   = tid & 3;             // d-quarter

    bool is64 = probe_is64(kpts_raw);
    int r, c, tg;
    read_point(kpts_raw, tags_raw, is64, idx, r, c, tg);

    int b = idx >> 9;
    int k = idx & (K_ - 1);
    const int d0 = h * (D_ / 4);
    const float* base = ebd + (size_t)b * D_ * H_ * W_ + (size_t)d0 * (H_ * W_)
                            + (size_t)r * W_ + (size_t)c;
    float* dstT = g_predT + (size_t)b * D_ * K_ + (size_t)d0 * K_ + k;
    float ns = 0.0f;
#pragma unroll
    for (int d = 0; d < D_ / 4; ++d) {
        float x = tf32_round(base[(size_t)d * (H_ * W_)]);
        dstT[(size_t)d * K_] = x;
        ns += x * x;
    }
    ns += __shfl_xor_sync(0xffffffffu, ns, 1);
    ns += __shfl_xor_sync(0xffffffffu, ns, 2);
    if (h == 0) {
        g_ns[idx]  = ns;
        g_tag[idx] = tg;
    }
}

// Symmetry-halved pairwise loss via tf32 mma.sync.m16n8k8.
// Gram C[k][l] = sum_d P[d][k] * P[d][l]:  m = k-row, n = l-col, red = d.
//   A (16x8 row-major): A[m][kd] = sI[d_base+kd][kw+m]
//   B (8x8 col-major):  B[kd][n] = sJ[d_base+kd][8*nt+n]
// Fragment maps (lane = 4*g + tig, g=lane>>2, tig=lane&3):
//   a0=A[g][tig]  a1=A[g+8][tig]  a2=A[g][tig+4]  a3=A[g+8][tig+4]
//   b0=B[tig][g]  b1=B[tig+4][g]
//   c0=C[g][2tig] c1=C[g][2tig+1] c2=C[g+8][2tig] c3=C[g+8][2tig+1]
// SPAD=72 row stride -> all fragment LDS are 32-bank conflict-free.
// psim = 2/(1+exp(x)) = 1 - tanh(x/2)  ->  e = tanh(arg) - neq.
__global__ __launch_bounds__(LTHREADS) void loss_kernel(float* __restrict__ out) {
    const int b = blockIdx.x / NPAIRS;
    int p = blockIdx.x % NPAIRS;
    int ti = 0;
    while (p >= NT - ti) { p -= (NT - ti); ++ti; }
    const int tj = ti + p;

    __shared__ float sI[D_ * SPAD];   // [d][k], padded  (9216 B)
    __shared__ float sJ[D_ * SPAD];   // [d][l], padded  (9216 B)
    __shared__ float nsI[TT], nsJ[TT];
    __shared__ int   tgI[TT], tgJ[TT];
    __shared__ float wsum[LTHREADS / 32];

    const int t = threadIdx.x;
    const float* srcI = g_predT + (size_t)b * D_ * K_ + ti * TT;
    const float* srcJ = g_predT + (size_t)b * D_ * K_ + tj * TT;

    // Fill: 512 float4 per tile, 4 per thread. Source row d = 16 float4
    // (stride K_), dest row stride SPAD floats (288 B, 16B-aligned).
#pragma unroll
    for (int rr = 0; rr < 4; ++rr) {
        int idx4 = t + rr * LTHREADS;     // 0..511
        int d  = idx4 >> 4;
        int j4 = idx4 & 15;
        float4 vi = *(const float4*)(srcI + (size_t)d * K_ + j4 * 4);
        float4 vj = *(const float4*)(srcJ + (size_t)d * K_ + j4 * 4);
        *(float4*)(sI + d * SPAD + j4 * 4) = vi;
        *(float4*)(sJ + d * SPAD + j4 * 4) = vj;
    }
    {
        const int baseI = b * K_ + ti * TT;
        const int baseJ = b * K_ + tj * TT;
        if (t < TT) {
            nsI[t] = g_ns[baseI + t];    tgI[t] = g_tag[baseI + t];
        } else {
            nsJ[t - TT] = g_ns[baseJ + t - TT];
            tgJ[t - TT] = g_tag[baseJ + t - TT];
        }
    }
    __syncthreads();

    const int warp = t >> 5;
    const int lane = t & 31;
    const int g    = lane >> 2;      // 0..7
    const int tig  = lane & 3;       // 0..3
    const int kw   = warp * 16;      // k-row base of this warp

    float c[8][4];
#pragma unroll
    for (int nt = 0; nt < 8; ++nt)
#pragma unroll
        for (int i = 0; i < 4; ++i) c[nt][i] = 0.0f;

#pragma unroll
    for (int ds = 0; ds < 4; ++ds) {
        const uint32* rA0 = (const uint32*)(sI + (8 * ds + tig) * SPAD);
        const uint32* rA4 = (const uint32*)(sI + (8 * ds + tig + 4) * SPAD);
        uint32 a0 = rA0[kw + g];
        uint32 a1 = rA0[kw + g + 8];
        uint32 a2 = rA4[kw + g];
        uint32 a3 = rA4[kw + g + 8];
        const uint32* rB0 = (const uint32*)(sJ + (8 * ds + tig) * SPAD);
        const uint32* rB4 = (const uint32*)(sJ + (8 * ds + tig + 4) * SPAD);
#pragma unroll
        for (int nt = 0; nt < 8; ++nt) {
            uint32 b0 = rB0[8 * nt + g];
            uint32 b1 = rB4[8 * nt + g];
            mma_tf32(c[nt][0], c[nt][1], c[nt][2], c[nt][3],
                     a0, a1, a2, a3, b0, b1);
        }
    }

    // Epilogue: 32 pairs per thread.
    // k rows: kw+g, kw+g+8; l cols per nt: 8nt+2tig, 8nt+2tig+1.
    const float nk0 = nsI[kw + g]     * (1.0f / 64.0f);
    const float nk1 = nsI[kw + g + 8] * (1.0f / 64.0f);
    const int   tk0 = tgI[kw + g];
    const int   tk1 = tgI[kw + g + 8];

    float lsum = 0.0f;
#pragma unroll
    for (int nt = 0; nt < 8; ++nt) {
        int l0 = 8 * nt + 2 * tig;
        int l1 = l0 + 1;
        float nl0 = nsJ[l0] * (1.0f / 64.0f);
        float nl1 = nsJ[l1] * (1.0f / 64.0f);
        int   tl0 = tgJ[l0];
        int   tl1 = tgJ[l1];

        float a00 = fmaf(c[nt][0], -1.0f / 32.0f, nk0 + nl0);
        float a01 = fmaf(c[nt][1], -1.0f / 32.0f, nk0 + nl1);
        float a10 = fmaf(c[nt][2], -1.0f / 32.0f, nk1 + nl0);
        float a11 = fmaf(c[nt][3], -1.0f / 32.0f, nk1 + nl1);
        float e00 = tanh_approx(a00) - ((tk0 != tl0) ? 1.0f : 0.0f);
        float e01 = tanh_approx(a01) - ((tk0 != tl1) ? 1.0f : 0.0f);
        float e10 = tanh_approx(a10) - ((tk1 != tl0) ? 1.0f : 0.0f);
        float e11 = tanh_approx(a11) - ((tk1 != tl1) ? 1.0f : 0.0f);
        lsum += e00 * e00 + e01 * e01 + e10 * e10 + e11 * e11;
    }

    // Block reduction (4 warps) + weighted atomic.
#pragma unroll
    for (int o = 16; o > 0; o >>= 1)
        lsum += __shfl_down_sync(0xffffffffu, lsum, o);
    if ((t & 31) == 0) wsum[t >> 5] = lsum;
    __syncthreads();
    if (t == 0) {
        float w = (ti == tj) ? 1.0f : 2.0f;
        float s = wsum[0] + wsum[1] + wsum[2] + wsum[3];
        atomicAdd(out, s * w * (1.0f / ((float)B_ * (float)K_ * (float)K_)));
    }
}

extern "C" void kernel_launch(void* const* d_in, const int* in_sizes, int n_in,
                              void* d_out, int out_size) {
    const float* ebd  = (const float*)d_in[0];
    const void*  kpts = (const void*)d_in[1];
    const void*  tags = (const void*)d_in[2];
    float* out = (float*)d_out;

    (void)in_sizes; (void)n_in; (void)out_size;

    gather_kernel<<<(B_ * K_ * 4 + GTHREADS - 1) / GTHREADS, GTHREADS>>>(
        ebd, kpts, tags, out);
    loss_kernel<<<NBLOCKS, LTHREADS>>>(out);
}